// round 1
// baseline (speedup 1.0000x reference)
#include <cuda_runtime.h>

// DTree_84061099917446 — soft decision tree forward pass.
// N=262144 rows, F=32 features, depth D=8, 255 internal nodes, 256 leaves, C=1.
//
// Algorithm: reference's coeff-product + matmul collapses to an upward tree
// recursion; implemented as pre-order DFS so every node's gating value g is
// computed exactly once per row (255 node evals/row, 8-deep stack).
// Dot products use packed fma.rn.f32x2 (FFMA2) across feature pairs.

#define F_      32
#define D_      8
#define NODES_  255
#define LEAVES_ 256
#define N_ROWS  262144
#define TPB     256

// Prologue results (scratch via __device__ globals — no allocation).
__device__ float g_W[NODES_ * F_];
__device__ float g_c[NODES_];

// ---------------------------------------------------------------------------
// Prologue: W = relu(feature_importances), c[n] = sum_f W[n,f]*sigmoid(fs[n,f])
// 255 blocks x 32 threads; warp-reduce for c. Negligible cost (~8K sigmoids).
// ---------------------------------------------------------------------------
__global__ void prep_kernel(const float* __restrict__ fi,
                            const float* __restrict__ fs) {
    int n = blockIdx.x;          // node 0..254
    int f = threadIdx.x;         // feature 0..31
    int idx = n * F_ + f;
    float w = fmaxf(fi[idx], 0.0f);
    float s = 1.0f / (1.0f + expf(-fs[idx]));   // precise sigmoid here
    g_W[idx] = w;
    float p = w * s;
    #pragma unroll
    for (int o = 16; o > 0; o >>= 1) p += __shfl_xor_sync(0xffffffffu, p, o);
    if (f == 0) g_c[n] = p;
}

// ---------------------------------------------------------------------------
// Packed f32x2 helpers (FFMA2 is only reachable via PTX fma.rn.f32x2).
// ---------------------------------------------------------------------------
__device__ __forceinline__ unsigned long long ffma2(unsigned long long a,
                                                    unsigned long long b,
                                                    unsigned long long c) {
#if __CUDA_ARCH__ >= 1000
    unsigned long long d;
    asm("fma.rn.f32x2 %0, %1, %2, %3;" : "=l"(d) : "l"(a), "l"(b), "l"(c));
    return d;
#else
    float2 fa, fb, fc, fd;
    fa = *reinterpret_cast<float2*>(&a);
    fb = *reinterpret_cast<float2*>(&b);
    fc = *reinterpret_cast<float2*>(&c);
    fd.x = fmaf(fa.x, fb.x, fc.x);
    fd.y = fmaf(fa.y, fb.y, fc.y);
    return *reinterpret_cast<unsigned long long*>(&fd);
#endif
}

__device__ __forceinline__ float2 upk(unsigned long long v) {
    float2 r;
    asm("mov.b64 {%0, %1}, %2;" : "=f"(r.x), "=f"(r.y) : "l"(v));
    return r;
}

// ---------------------------------------------------------------------------
// Main kernel: one thread per row. DFS over the complete binary tree.
//   - All threads traverse the identical node sequence -> uniform branches,
//     broadcast LDS of W/c/cls (conflict-free).
//   - For leaf l (l>0): t = ctz(l); resume prod from stack at divergence depth
//     D-1-t and evaluate the t new nodes at depths D-t .. D-1 (all left-
//     descents: trailing bits of l are 0, so "always multiply by g, stash
//     prod*(1-g) for the right branch" is exact).
// ---------------------------------------------------------------------------
__global__ void __launch_bounds__(TPB)
dtree_kernel(const float* __restrict__ x,
             const float* __restrict__ cls,
             float* __restrict__ out) {
    __shared__ __align__(16) float sW[NODES_ * F_];   // 32640 B
    __shared__ float sc[NODES_];
    __shared__ float scls[LEAVES_];

    for (int i = threadIdx.x; i < NODES_ * F_; i += TPB) sW[i] = g_W[i];
    if (threadIdx.x < NODES_)  sc[threadIdx.x]   = g_c[threadIdx.x];
    if (threadIdx.x < LEAVES_) scls[threadIdx.x] = cls[threadIdx.x];
    __syncthreads();

    int row = blockIdx.x * TPB + threadIdx.x;

    // Row features as 16 packed f32x2 (feature pairs), loaded 128b at a time.
    unsigned long long xv[16];
    const ulonglong2* xp =
        reinterpret_cast<const ulonglong2*>(x + (size_t)row * F_);
    #pragma unroll
    for (int i = 0; i < 8; ++i) {
        ulonglong2 v = xp[i];
        xv[2 * i]     = v.x;
        xv[2 * i + 1] = v.y;
    }

    float stk[D_];
    float prod    = 1.0f;
    float acc_out = 0.0f;

    #pragma unroll 1
    for (int l = 0; l < LEAVES_; ++l) {
        int dstart;
        if (l == 0) {
            dstart = 0;
            prod   = 1.0f;
        } else {
            int t  = __ffs(l) - 1;        // trailing zeros of l
            dstart = D_ - t;
            prod   = stk[D_ - 1 - t];     // right-branch product at divergence
        }
        #pragma unroll 1
        for (int d = dstart; d < D_; ++d) {
            int n = ((1 << d) - 1) + (l >> (D_ - d));

            const ulonglong2* wp =
                reinterpret_cast<const ulonglong2*>(&sW[n * F_]);
            unsigned long long a0 = 0ull, a1 = 0ull;   // packed (0,0)
            #pragma unroll
            for (int i = 0; i < 8; ++i) {
                ulonglong2 w = wp[i];                  // LDS.128 broadcast
                a0 = ffma2(xv[2 * i],     w.x, a0);
                a1 = ffma2(xv[2 * i + 1], w.y, a1);
            }
            float2 s0 = upk(a0), s1 = upk(a1);
            float z = (s0.x + s0.y) + (s1.x + s1.y) - sc[n];

            float e = __expf(-z);                       // FMUL + MUFU.EX2
            float g = __fdividef(1.0f, 1.0f + e);       // MUFU.RCP path

            stk[d] = prod * (1.0f - g);                 // right-branch stash
            prod  *= g;                                 // left descent
        }
        acc_out += prod * scls[l];
    }

    out[row] = acc_out;
}

// ---------------------------------------------------------------------------
extern "C" void kernel_launch(void* const* d_in, const int* in_sizes, int n_in,
                              void* d_out, int out_size) {
    const float* x   = (const float*)d_in[0];   // (N, 32)
    const float* fi  = (const float*)d_in[1];   // (255*32, 1)
    const float* fs  = (const float*)d_in[2];   // (255*32, 1)
    const float* cls = (const float*)d_in[3];   // (256, 1)
    float* out = (float*)d_out;                 // (N, 1) float32

    prep_kernel<<<NODES_, 32>>>(fi, fs);
    dtree_kernel<<<N_ROWS / TPB, TPB>>>(x, cls, out);
}

// round 3
// speedup vs baseline: 1.1118x; 1.1118x over previous
#include <cuda_runtime.h>

// DTree_84061099917446 — soft decision tree forward pass.
// N=262144 rows, F=32, depth 8, 255 nodes, 256 leaves, C=1.
//
// R3 (= R2 resubmit; R2 hit an infra container failure, kernel never ran):
// two rows per thread (halves W LDS traffic per row) + register-resident
// DFS stack via fall-through switch (kills local-memory LDL/STL traffic).
// Dot products use packed fma.rn.f32x2; c pre-negated/packed into accumulator
// init; prod*(1-g) as a single FFMA.

#define F_      32
#define D_      8
#define NODES_  255
#define LEAVES_ 256
#define N_ROWS  262144
#define TPB     256

typedef unsigned long long u64;

// Prologue results (scratch via __device__ globals — no allocation).
__device__ float g_W[NODES_ * F_];
__device__ u64   g_c2[NODES_];     // packed float2 (-c, 0.0f)

// ---------------------------------------------------------------------------
// Prologue: W = relu(fi), c[n] = sum_f W[n,f]*sigmoid(fs[n,f]); store (-c,0).
// ---------------------------------------------------------------------------
__global__ void prep_kernel(const float* __restrict__ fi,
                            const float* __restrict__ fs) {
    int n = blockIdx.x;          // node 0..254
    int f = threadIdx.x;         // feature 0..31
    int idx = n * F_ + f;
    float w = fmaxf(fi[idx], 0.0f);
    float s = 1.0f / (1.0f + expf(-fs[idx]));
    g_W[idx] = w;
    float p = w * s;
    #pragma unroll
    for (int o = 16; o > 0; o >>= 1) p += __shfl_xor_sync(0xffffffffu, p, o);
    if (f == 0) {
        float2 v; v.x = -p; v.y = 0.0f;
        g_c2[n] = *reinterpret_cast<u64*>(&v);
    }
}

// ---------------------------------------------------------------------------
// Packed f32x2 helpers.
// ---------------------------------------------------------------------------
__device__ __forceinline__ u64 ffma2(u64 a, u64 b, u64 c) {
    u64 d;
    asm("fma.rn.f32x2 %0, %1, %2, %3;" : "=l"(d) : "l"(a), "l"(b), "l"(c));
    return d;
}

// (a + b) packed, then horizontal sum -> scalar
__device__ __forceinline__ float psum(u64 a, u64 b) {
    u64 s;
    asm("add.rn.f32x2 %0, %1, %2;" : "=l"(s) : "l"(a), "l"(b));
    float lo, hi;
    asm("mov.b64 {%0, %1}, %2;" : "=f"(lo), "=f"(hi) : "l"(s));
    return lo + hi;
}

__device__ __forceinline__ float fsigmoid(float z) {
    float e = __expf(-z);            // FMUL + MUFU.EX2
    float d = 1.0f + e;              // FADD
    float g;
    asm("rcp.approx.f32 %0, %1;" : "=f"(g) : "f"(d));   // MUFU.RCP
    return g;
}

// ---------------------------------------------------------------------------
// Main kernel. Thread handles rows rowA, rowB. DFS over even leaves with
// register stack; odd leaf = stk[7] (no extra eval).
// ---------------------------------------------------------------------------
// Evaluate node at depth d on the path to leaf l (left descent).
#define EVAL(d) { \
    int n_ = ((1 << (d)) - 1) + (l >> (8 - (d))); \
    const ulonglong2* wp_ = reinterpret_cast<const ulonglong2*>(sW + n_ * F_); \
    u64 A0 = sc2[n_], B0 = A0;          /* init = (-c, 0) */ \
    u64 A1 = 0ull,    B1 = 0ull; \
    _Pragma("unroll") \
    for (int i_ = 0; i_ < 8; ++i_) { \
        ulonglong2 w_ = wp_[i_];        /* LDS.128 broadcast, reused 2 rows */ \
        A0 = ffma2(xa[2*i_],   w_.x, A0); \
        A1 = ffma2(xa[2*i_+1], w_.y, A1); \
        B0 = ffma2(xb[2*i_],   w_.x, B0); \
        B1 = ffma2(xb[2*i_+1], w_.y, B1); \
    } \
    float ga = fsigmoid(psum(A0, A1)); \
    float gb = fsigmoid(psum(B0, B1)); \
    sA##d = fmaf(-prodA, ga, prodA);    /* prod*(1-g), one FFMA */ \
    sB##d = fmaf(-prodB, gb, prodB); \
    prodA *= ga; \
    prodB *= gb; \
}

__global__ void __launch_bounds__(TPB, 2)
dtree_kernel(const float* __restrict__ x,
             const float* __restrict__ cls,
             float* __restrict__ out) {
    __shared__ __align__(16) float sW[NODES_ * F_];   // 32640 B
    __shared__ u64   sc2[NODES_];
    __shared__ __align__(8) float scls[LEAVES_];

    for (int i = threadIdx.x; i < NODES_ * F_; i += TPB) sW[i] = g_W[i];
    if (threadIdx.x < NODES_)  sc2[threadIdx.x]  = g_c2[threadIdx.x];
    if (threadIdx.x < LEAVES_) scls[threadIdx.x] = cls[threadIdx.x];
    __syncthreads();

    int rowA = blockIdx.x * (TPB * 2) + threadIdx.x;
    int rowB = rowA + TPB;

    // Row features as 16 packed f32x2 each (feature pairs).
    u64 xa[16], xb[16];
    {
        const ulonglong2* pa = reinterpret_cast<const ulonglong2*>(x + (size_t)rowA * F_);
        const ulonglong2* pb = reinterpret_cast<const ulonglong2*>(x + (size_t)rowB * F_);
        #pragma unroll
        for (int i = 0; i < 8; ++i) {
            ulonglong2 va = pa[i]; xa[2*i] = va.x; xa[2*i+1] = va.y;
            ulonglong2 vb = pb[i]; xb[2*i] = vb.x; xb[2*i+1] = vb.y;
        }
    }

    float sA0=0,sA1=0,sA2=0,sA3=0,sA4=0,sA5=0,sA6=0,sA7=0;
    float sB0=0,sB1=0,sB2=0,sB3=0,sB4=0,sB5=0,sB6=0,sB7=0;
    float prodA = 1.0f, prodB = 1.0f;
    float accA = 0.0f, accB = 0.0f;

    #pragma unroll 1
    for (int k = 0; k < LEAVES_ / 2; ++k) {
        const int l = k * 2;
        int dstart;
        if (k == 0) {
            dstart = 0;
            prodA = 1.0f; prodB = 1.0f;
        } else {
            int t = __ffs(l) - 1;        // trailing zeros, >= 1 (l even)
            dstart = D_ - t;             // 1..7
            switch (dstart - 1) {        // resume from right-branch stash
                case 0: prodA = sA0; prodB = sB0; break;
                case 1: prodA = sA1; prodB = sB1; break;
                case 2: prodA = sA2; prodB = sB2; break;
                case 3: prodA = sA3; prodB = sB3; break;
                case 4: prodA = sA4; prodB = sB4; break;
                case 5: prodA = sA5; prodB = sB5; break;
                case 6: prodA = sA6; prodB = sB6; break;
            }
        }
        switch (dstart) {                // fall-through: eval depths dstart..7
            case 0: EVAL(0);
            case 1: EVAL(1);
            case 2: EVAL(2);
            case 3: EVAL(3);
            case 4: EVAL(4);
            case 5: EVAL(5);
            case 6: EVAL(6);
            case 7: EVAL(7);
        }
        // leaf 2k uses prod (ends in *g7); leaf 2k+1 uses stk[7] = prod*(1-g7)
        float2 c2 = reinterpret_cast<const float2*>(scls)[k];
        accA = fmaf(prodA, c2.x, accA);
        accA = fmaf(sA7,   c2.y, accA);
        accB = fmaf(prodB, c2.x, accB);
        accB = fmaf(sB7,   c2.y, accB);
    }

    out[rowA] = accA;
    out[rowB] = accB;
}

// ---------------------------------------------------------------------------
extern "C" void kernel_launch(void* const* d_in, const int* in_sizes, int n_in,
                              void* d_out, int out_size) {
    const float* x   = (const float*)d_in[0];   // (N, 32)
    const float* fi  = (const float*)d_in[1];   // (255*32, 1)
    const float* fs  = (const float*)d_in[2];   // (255*32, 1)
    const float* cls = (const float*)d_in[3];   // (256, 1)
    float* out = (float*)d_out;                 // (N, 1) float32

    prep_kernel<<<NODES_, 32>>>(fi, fs);
    dtree_kernel<<<N_ROWS / (TPB * 2), TPB>>>(x, cls, out);
}

// round 5
// speedup vs baseline: 1.2611x; 1.1343x over previous
#include <cuda_runtime.h>

// DTree_84061099917446 — soft decision tree forward pass.
// N=262144 rows, F=32, depth 8, 255 nodes, 256 leaves, C=1.
//
// R5 (= R4 resubmit; R4 hit the recurring infra container failure, kernel
// never ran): fully branch-free. Template recursion subtree<DEPTH,NODE>
// unrolls the entire 255-node DFS at compile time (node indices literal, no
// switch, no __ffs, no loop). W pre-scaled by -log2(e) so the gate is
// EX2+FADD+RCP. Depth-7 nodes fold their two leaves into 2 FFMAs via
// (clsR, clsL-clsR). Two rows per thread share every W LDS.128.

#define F_      32
#define NODES_  255
#define LEAVES_ 256
#define N_ROWS  262144
#define TPB     256
#define LOG2E_F 1.4426950408889634f

typedef unsigned long long u64;

// Prologue results (scratch via __device__ globals — no allocation).
__device__ float g_W[NODES_ * F_];   // -log2e * relu(fi)
__device__ u64   g_c2[NODES_];       // packed float2 (+log2e * c, 0)

// ---------------------------------------------------------------------------
// Prologue. c[n] = sum_f relu(fi)*sigmoid(fs) (unscaled W); store scaled W.
// ---------------------------------------------------------------------------
__global__ void prep_kernel(const float* __restrict__ fi,
                            const float* __restrict__ fs) {
    int n = blockIdx.x;          // node 0..254
    int f = threadIdx.x;         // feature 0..31
    int idx = n * F_ + f;
    float w = fmaxf(fi[idx], 0.0f);
    float s = 1.0f / (1.0f + expf(-fs[idx]));
    g_W[idx] = -LOG2E_F * w;
    float p = w * s;
    #pragma unroll
    for (int o = 16; o > 0; o >>= 1) p += __shfl_xor_sync(0xffffffffu, p, o);
    if (f == 0) {
        float2 v; v.x = LOG2E_F * p; v.y = 0.0f;
        g_c2[n] = *reinterpret_cast<u64*>(&v);
    }
}

// ---------------------------------------------------------------------------
// Packed f32x2 / gate helpers.
// ---------------------------------------------------------------------------
__device__ __forceinline__ u64 ffma2(u64 a, u64 b, u64 c) {
    u64 d;
    asm("fma.rn.f32x2 %0, %1, %2, %3;" : "=l"(d) : "l"(a), "l"(b), "l"(c));
    return d;
}

// horizontal sum of two packed f32x2 accumulators -> scalar
__device__ __forceinline__ float psum(u64 a, u64 b) {
    u64 s;
    asm("add.rn.f32x2 %0, %1, %2;" : "=l"(s) : "l"(a), "l"(b));
    float lo, hi;
    asm("mov.b64 {%0, %1}, %2;" : "=f"(lo), "=f"(hi) : "l"(s));
    return lo + hi;
}

// y = -log2e * z  ->  g = sigmoid(z) = 1 / (1 + 2^y)
__device__ __forceinline__ float fgate(float y) {
    float e, g;
    asm("ex2.approx.f32 %0, %1;" : "=f"(e) : "f"(y));
    float d = 1.0f + e;
    asm("rcp.approx.f32 %0, %1;" : "=f"(g) : "f"(d));
    return g;
}

// ---------------------------------------------------------------------------
// Compile-time-unrolled DFS. NODE is a literal at every instantiation.
// Left child multiplies by g, right child by (1-g). Depth-7 nodes fold their
// two leaves: acc += prod * (clsR + g*(clsL - clsR)).
// ---------------------------------------------------------------------------
template<int DEPTH, int NODE>
__device__ __forceinline__ void subtree(const float*  __restrict__ sW,
                                        const u64*    __restrict__ sc2,
                                        const float2* __restrict__ spair,
                                        const u64 (&xa)[16], const u64 (&xb)[16],
                                        float prodA, float prodB,
                                        float& accA, float& accB) {
    const ulonglong2* wp =
        reinterpret_cast<const ulonglong2*>(sW + NODE * F_);
    u64 A0 = sc2[NODE], B0 = A0;       // init = (+log2e*c, 0)
    u64 A1 = 0ull,      B1 = 0ull;
    #pragma unroll
    for (int i = 0; i < 8; ++i) {
        ulonglong2 w = wp[i];          // LDS.128 broadcast, reused by 2 rows
        A0 = ffma2(xa[2*i],   w.x, A0);
        A1 = ffma2(xa[2*i+1], w.y, A1);
        B0 = ffma2(xb[2*i],   w.x, B0);
        B1 = ffma2(xb[2*i+1], w.y, B1);
    }
    float ga = fgate(psum(A0, A1));
    float gb = fgate(psum(B0, B1));

    if constexpr (DEPTH == 7) {
        float2 pr = spair[NODE - 127];           // (clsR, clsL - clsR)
        accA = fmaf(prodA, fmaf(ga, pr.y, pr.x), accA);
        accB = fmaf(prodB, fmaf(gb, pr.y, pr.x), accB);
    } else {
        float rA = fmaf(-prodA, ga, prodA);      // prod*(1-g)
        float rB = fmaf(-prodB, gb, prodB);
        subtree<DEPTH + 1, 2 * NODE + 1>(sW, sc2, spair, xa, xb,
                                         prodA * ga, prodB * gb, accA, accB);
        subtree<DEPTH + 1, 2 * NODE + 2>(sW, sc2, spair, xa, xb,
                                         rA, rB, accA, accB);
    }
}

// ---------------------------------------------------------------------------
__global__ void __launch_bounds__(TPB, 2)
dtree_kernel(const float* __restrict__ x,
             const float* __restrict__ cls,
             float* __restrict__ out) {
    __shared__ __align__(16) float  sW[NODES_ * F_];   // 32640 B
    __shared__ u64    sc2[NODES_];
    __shared__ float2 spair[LEAVES_ / 2];

    for (int i = threadIdx.x; i < NODES_ * F_; i += TPB) sW[i] = g_W[i];
    if (threadIdx.x < NODES_) sc2[threadIdx.x] = g_c2[threadIdx.x];
    if (threadIdx.x < LEAVES_ / 2) {
        float l = cls[2 * threadIdx.x];
        float r = cls[2 * threadIdx.x + 1];
        spair[threadIdx.x] = make_float2(r, l - r);
    }
    __syncthreads();

    int rowA = blockIdx.x * (TPB * 2) + threadIdx.x;
    int rowB = rowA + TPB;

    // Row features as 16 packed f32x2 each (feature pairs).
    u64 xa[16], xb[16];
    {
        const ulonglong2* pa = reinterpret_cast<const ulonglong2*>(x + (size_t)rowA * F_);
        const ulonglong2* pb = reinterpret_cast<const ulonglong2*>(x + (size_t)rowB * F_);
        #pragma unroll
        for (int i = 0; i < 8; ++i) {
            ulonglong2 va = pa[i]; xa[2*i] = va.x; xa[2*i+1] = va.y;
            ulonglong2 vb = pb[i]; xb[2*i] = vb.x; xb[2*i+1] = vb.y;
        }
    }

    float accA = 0.0f, accB = 0.0f;
    subtree<0, 0>(sW, sc2, spair, xa, xb, 1.0f, 1.0f, accA, accB);

    out[rowA] = accA;
    out[rowB] = accB;
}

// ---------------------------------------------------------------------------
extern "C" void kernel_launch(void* const* d_in, const int* in_sizes, int n_in,
                              void* d_out, int out_size) {
    const float* x   = (const float*)d_in[0];   // (N, 32)
    const float* fi  = (const float*)d_in[1];   // (255*32, 1)
    const float* fs  = (const float*)d_in[2];   // (255*32, 1)
    const float* cls = (const float*)d_in[3];   // (256, 1)
    float* out = (float*)d_out;                 // (N, 1) float32

    prep_kernel<<<NODES_, 32>>>(fi, fs);
    dtree_kernel<<<N_ROWS / (TPB * 2), TPB>>>(x, cls, out);
}